// round 4
// baseline (speedup 1.0000x reference)
#include <cuda_runtime.h>

#define B_  4
#define L_  2048
#define D_  1024
#define H_  16
#define DK_ 64
#define M_  (B_*L_)   // 8192

// Scratch (device globals — no allocation allowed)
__device__ float g_Qp[M_*D_];
__device__ float g_Kp[M_*D_];
__device__ float g_Vp[M_*D_];
__device__ float g_Ao[M_*D_];

// ---------------------------------------------------------------------------
// SGEMM: Y[M,N] = X[M,K] * W[N,K]^T + bias[N]   (torch Linear)
// M=8192, N=1024, K=1024. 128x128 tile, BK=8, 256 threads, 8x8 per thread.
// ---------------------------------------------------------------------------
__global__ __launch_bounds__(256)
void sgemm_nt_bias(const float* __restrict__ X, const float* __restrict__ W,
                   const float* __restrict__ bias, float* __restrict__ Y) {
    __shared__ float As[8][128];
    __shared__ float Bs[8][128];

    const int tid = threadIdx.x;
    const int m0  = blockIdx.y * 128;
    const int n0  = blockIdx.x * 128;
    const int tx  = tid & 15;   // col group (8 cols)
    const int ty  = tid >> 4;   // row group (8 rows)

    const int lrow = tid >> 1;          // 0..127
    const int lk   = (tid & 1) * 4;     // 0 or 4
    const float* Xp = X + (size_t)(m0 + lrow) * D_ + lk;
    const float* Wp = W + (size_t)(n0 + lrow) * D_ + lk;

    float acc[8][8];
#pragma unroll
    for (int i = 0; i < 8; i++)
#pragma unroll
        for (int j = 0; j < 8; j++) acc[i][j] = 0.f;

    for (int k0 = 0; k0 < D_; k0 += 8) {
        float4 xa = *(const float4*)(Xp + k0);
        float4 wb = *(const float4*)(Wp + k0);
        As[lk+0][lrow] = xa.x; As[lk+1][lrow] = xa.y;
        As[lk+2][lrow] = xa.z; As[lk+3][lrow] = xa.w;
        Bs[lk+0][lrow] = wb.x; Bs[lk+1][lrow] = wb.y;
        Bs[lk+2][lrow] = wb.z; Bs[lk+3][lrow] = wb.w;
        __syncthreads();

#pragma unroll
        for (int kk = 0; kk < 8; kk++) {
            float4 a0 = *(const float4*)&As[kk][ty*8];
            float4 a1 = *(const float4*)&As[kk][ty*8+4];
            float4 b0 = *(const float4*)&Bs[kk][tx*8];
            float4 b1 = *(const float4*)&Bs[kk][tx*8+4];
            float ra[8] = {a0.x,a0.y,a0.z,a0.w,a1.x,a1.y,a1.z,a1.w};
            float rb[8] = {b0.x,b0.y,b0.z,b0.w,b1.x,b1.y,b1.z,b1.w};
#pragma unroll
            for (int i = 0; i < 8; i++)
#pragma unroll
                for (int j = 0; j < 8; j++)
                    acc[i][j] += ra[i] * rb[j];
        }
        __syncthreads();
    }

    float4 bv0 = *(const float4*)&bias[n0 + tx*8];
    float4 bv1 = *(const float4*)&bias[n0 + tx*8 + 4];
    float rbias[8] = {bv0.x,bv0.y,bv0.z,bv0.w,bv1.x,bv1.y,bv1.z,bv1.w};

#pragma unroll
    for (int i = 0; i < 8; i++) {
        float* yrow = Y + (size_t)(m0 + ty*8 + i) * D_ + n0 + tx*8;
        float4 o0, o1;
        o0.x = acc[i][0] + rbias[0]; o0.y = acc[i][1] + rbias[1];
        o0.z = acc[i][2] + rbias[2]; o0.w = acc[i][3] + rbias[3];
        o1.x = acc[i][4] + rbias[4]; o1.y = acc[i][5] + rbias[5];
        o1.z = acc[i][6] + rbias[6]; o1.w = acc[i][7] + rbias[7];
        *(float4*)(yrow)     = o0;
        *(float4*)(yrow + 4) = o1;
    }
}

// ---------------------------------------------------------------------------
// Flash attention, causal, fp32.
// Grid: (L/128, H, B). 256 threads: tx=tid&15 (4 cols), ty=tid>>4 (8 rows).
// Per CTA: 128 queries; loop over 64-wide key blocks up to the diagonal.
// Smem (dynamic, pitch 65 to kill bank conflicts):
//   Qs[128][65], Ks[64][65] (TRANSPOSED: Ks[d*65+c]), Vs[64][65], Ps[128][65]
// ---------------------------------------------------------------------------
#define FLASH_SMEM_FLOATS (128*65 + 64*65 + 64*65 + 128*65)
#define FLASH_SMEM_BYTES  (FLASH_SMEM_FLOATS * 4)

__device__ __forceinline__ float redmax16(float v) {
#pragma unroll
    for (int o = 8; o >= 1; o >>= 1)
        v = fmaxf(v, __shfl_xor_sync(0xffffffffu, v, o));
    return v;
}
__device__ __forceinline__ float redsum16(float v) {
#pragma unroll
    for (int o = 8; o >= 1; o >>= 1)
        v += __shfl_xor_sync(0xffffffffu, v, o);
    return v;
}

__global__ __launch_bounds__(256)
void flash_attn_causal(const float* __restrict__ Qp, const float* __restrict__ Kp,
                       const float* __restrict__ Vp, float* __restrict__ Ao) {
    extern __shared__ float sm[];
    float* Qs = sm;                 // [128][65]
    float* Ks = Qs + 128*65;        // [64][65]  transposed: Ks[d*65 + c]
    float* Vs = Ks + 64*65;         // [64][65]  Vs[c*65 + d]
    float* Ps = Vs + 64*65;         // [128][65]

    const int tid = threadIdx.x;
    const int tx  = tid & 15;       // col group: cols tx*4 .. tx*4+3
    const int ty  = tid >> 4;       // row group: rows ty*8 .. ty*8+7
    const int qb  = blockIdx.x;     // 0..15 (query block of 128)
    const int h   = blockIdx.y;
    const int b   = blockIdx.z;

    const int rowbase = b * L_ + qb * 128;   // global row of query 0 of this CTA
    const int colbase = h * DK_;

    // Load Q block (scaled by 1/sqrt(DK) = 0.125)
    {
        const int r     = tid >> 1;          // 0..127
        const int dbase = (tid & 1) * 32;    // 0 or 32
        const float* src = Qp + (size_t)(rowbase + r) * D_ + colbase + dbase;
        float* dst = Qs + r * 65 + dbase;
#pragma unroll
        for (int i = 0; i < 8; i++) {
            float4 vq = *(const float4*)(src + i * 4);
            dst[i*4+0] = vq.x * 0.125f; dst[i*4+1] = vq.y * 0.125f;
            dst[i*4+2] = vq.z * 0.125f; dst[i*4+3] = vq.w * 0.125f;
        }
    }

    float m[8], l[8], O[8][4];
#pragma unroll
    for (int i = 0; i < 8; i++) {
        m[i] = -1e30f; l[i] = 0.f;
        O[i][0] = O[i][1] = O[i][2] = O[i][3] = 0.f;
    }

    const int nkb = 2 * qb + 2;     // key blocks of 64, through the diagonal
    const int kvc   = tid >> 2;          // 0..63 (key row this thread loads)
    const int kvd   = (tid & 3) * 16;    // d segment

    for (int kb = 0; kb < nkb; kb++) {
        // ---- load K (transposed) and V ----
        {
            const size_t grow = (size_t)(b * L_ + kb * 64 + kvc) * D_ + colbase + kvd;
            const float* ksrc = Kp + grow;
            const float* vsrc = Vp + grow;
#pragma unroll
            for (int i = 0; i < 4; i++) {
                float4 kv = *(const float4*)(ksrc + i * 4);
                const int d0 = kvd + i * 4;
                Ks[(d0+0)*65 + kvc] = kv.x;
                Ks[(d0+1)*65 + kvc] = kv.y;
                Ks[(d0+2)*65 + kvc] = kv.z;
                Ks[(d0+3)*65 + kvc] = kv.w;
                float4 vv = *(const float4*)(vsrc + i * 4);
                float* vd = Vs + kvc * 65 + d0;
                vd[0] = vv.x; vd[1] = vv.y; vd[2] = vv.z; vd[3] = vv.w;
            }
        }
        __syncthreads();

        // ---- S = (Q*scale) @ K^T ----
        float S[8][4];
#pragma unroll
        for (int i = 0; i < 8; i++)
            S[i][0] = S[i][1] = S[i][2] = S[i][3] = 0.f;

        const float* qptr = Qs + ty * 8 * 65;
        const float* kptr = Ks + tx * 4;
#pragma unroll 8
        for (int d = 0; d < 64; d++) {
            const float rk0 = kptr[d*65 + 0];
            const float rk1 = kptr[d*65 + 1];
            const float rk2 = kptr[d*65 + 2];
            const float rk3 = kptr[d*65 + 3];
#pragma unroll
            for (int i = 0; i < 8; i++) {
                const float rq = qptr[i*65 + d];
                S[i][0] += rq * rk0; S[i][1] += rq * rk1;
                S[i][2] += rq * rk2; S[i][3] += rq * rk3;
            }
        }

        // ---- causal mask (only blocks touching the diagonal) ----
        if (kb >= 2 * qb) {
#pragma unroll
            for (int i = 0; i < 8; i++) {
                const int qg = qb * 128 + ty * 8 + i;
#pragma unroll
                for (int j = 0; j < 4; j++) {
                    const int kg = kb * 64 + tx * 4 + j;
                    if (kg > qg) S[i][j] = -1e30f;
                }
            }
        }

        // ---- online softmax update ----
        float* pptr = Ps + ty * 8 * 65 + tx * 4;
#pragma unroll
        for (int i = 0; i < 8; i++) {
            float mx = fmaxf(fmaxf(S[i][0], S[i][1]), fmaxf(S[i][2], S[i][3]));
            mx = redmax16(mx);
            const float mn = fmaxf(m[i], mx);
            const float alpha = __expf(m[i] - mn);
            const float p0 = __expf(S[i][0] - mn);
            const float p1 = __expf(S[i][1] - mn);
            const float p2 = __expf(S[i][2] - mn);
            const float p3 = __expf(S[i][3] - mn);
            float rs = p0 + p1 + p2 + p3;
            rs = redsum16(rs);
            l[i] = l[i] * alpha + rs;
            m[i] = mn;
            O[i][0] *= alpha; O[i][1] *= alpha;
            O[i][2] *= alpha; O[i][3] *= alpha;
            pptr[i*65 + 0] = p0; pptr[i*65 + 1] = p1;
            pptr[i*65 + 2] = p2; pptr[i*65 + 3] = p3;
        }
        __syncthreads();

        // ---- O += P @ V ----
        const float* ppr = Ps + ty * 8 * 65;
        const float* vpr = Vs + tx * 4;
#pragma unroll 8
        for (int c = 0; c < 64; c++) {
            const float rv0 = vpr[c*65 + 0];
            const float rv1 = vpr[c*65 + 1];
            const float rv2 = vpr[c*65 + 2];
            const float rv3 = vpr[c*65 + 3];
#pragma unroll
            for (int i = 0; i < 8; i++) {
                const float rp = ppr[i*65 + c];
                O[i][0] += rp * rv0; O[i][1] += rp * rv1;
                O[i][2] += rp * rv2; O[i][3] += rp * rv3;
            }
        }
        __syncthreads();   // before next iteration overwrites Ks/Vs
    }

    // ---- normalize and write out: Ao[b*L + q, h*64 + d] ----
#pragma unroll
    for (int i = 0; i < 8; i++) {
        const float inv = 1.0f / l[i];
        float* dst = Ao + (size_t)(rowbase + ty * 8 + i) * D_ + colbase + tx * 4;
        dst[0] = O[i][0] * inv; dst[1] = O[i][1] * inv;
        dst[2] = O[i][2] * inv; dst[3] = O[i][3] * inv;
    }
}

// ---------------------------------------------------------------------------
extern "C" void kernel_launch(void* const* d_in, const int* in_sizes, int n_in,
                              void* d_out, int out_size) {
    (void)in_sizes; (void)n_in; (void)out_size;
    const float* q    = (const float*)d_in[0];
    const float* k    = (const float*)d_in[1];
    const float* v    = (const float*)d_in[2];
    const float* wq_w = (const float*)d_in[3];
    const float* wq_b = (const float*)d_in[4];
    const float* wk_w = (const float*)d_in[5];
    const float* wk_b = (const float*)d_in[6];
    const float* wv_w = (const float*)d_in[7];
    const float* wv_b = (const float*)d_in[8];
    const float* wo_w = (const float*)d_in[9];
    const float* wo_b = (const float*)d_in[10];

    float *Qp, *Kp, *Vp, *Ao;
    cudaGetSymbolAddress((void**)&Qp, g_Qp);
    cudaGetSymbolAddress((void**)&Kp, g_Kp);
    cudaGetSymbolAddress((void**)&Vp, g_Vp);
    cudaGetSymbolAddress((void**)&Ao, g_Ao);

    dim3 gg(D_/128, M_/128);   // (8, 64)
    sgemm_nt_bias<<<gg, 256>>>(q, wq_w, wq_b, Qp);
    sgemm_nt_bias<<<gg, 256>>>(k, wk_w, wk_b, Kp);
    sgemm_nt_bias<<<gg, 256>>>(v, wv_w, wv_b, Vp);

    cudaFuncSetAttribute(flash_attn_causal,
                         cudaFuncAttributeMaxDynamicSharedMemorySize,
                         FLASH_SMEM_BYTES);
    flash_attn_causal<<<dim3(L_/128, H_, B_), 256, FLASH_SMEM_BYTES>>>(Qp, Kp, Vp, Ao);

    sgemm_nt_bias<<<gg, 256>>>(Ao, wo_w, wo_b, (float*)d_out);
}

// round 7
// speedup vs baseline: 1.6830x; 1.6830x over previous
#include <cuda_runtime.h>
#include <cstdint>

#define B_  4
#define L_  2048
#define D_  1024
#define H_  16
#define DK_ 64
#define M_  (B_*L_)   // 8192

// Scratch (device globals — no allocation allowed)
__device__ float g_Qp[M_*D_];
__device__ float g_Kp[M_*D_];
__device__ float g_Vp[M_*D_];
__device__ float g_Ao[M_*D_];

// ---------------------------------------------------------------------------
// TF32 tensor-core GEMM: Y[M,N] = X[M,K] * W[N,K]^T + bias[N]  (torch Linear)
// M=8192, N=1024, K=1024.
// CTA tile 128x128, BK=16, 256 threads = 8 warps in a 2(m) x 4(n) grid,
// each warp computes 64x32 via 4x4 tiles of mma.sync.m16n8k8.tf32.
// cp.async double-buffered smem; rows padded to 20 floats (conflict-free
// scalar fragment loads: 8 row-groups x 4 k-lanes = exact 32-bank partition).
// ---------------------------------------------------------------------------
__device__ __forceinline__ uint32_t f2tf32(float f) {
    uint32_t r;
    asm("cvt.rna.tf32.f32 %0, %1;" : "=r"(r) : "f"(f));
    return r;
}

__global__ __launch_bounds__(256)
void gemm_tf32_nt_bias(const float* __restrict__ X, const float* __restrict__ W,
                       const float* __restrict__ bias, float* __restrict__ Y) {
    __shared__ float As[2][128][20];
    __shared__ float Bs[2][128][20];

    const int tid  = threadIdx.x;
    const int m0   = blockIdx.y * 128;
    const int n0   = blockIdx.x * 128;
    const int warp = tid >> 5;
    const int lane = tid & 31;
    const int wm   = warp >> 2;       // 0..1  (64-row slab)
    const int wn   = warp & 3;        // 0..3  (32-col slab)
    const int g    = lane >> 2;       // groupID 0..7
    const int tg   = lane & 3;        // thread-in-group 0..3

    // cp.async load mapping: 512 row-segments per matrix, 2 per thread
    const int lr = tid >> 2;          // 0..63 -> rows lr, lr+64
    const int sg = (tid & 3) * 4;     // k segment start (floats)

    float c[4][4][4];
#pragma unroll
    for (int mt = 0; mt < 4; mt++)
#pragma unroll
        for (int nt = 0; nt < 4; nt++)
#pragma unroll
            for (int e = 0; e < 4; e++) c[mt][nt][e] = 0.f;

#define ISSUE_STAGE(KT, BUF)                                                     \
    do {                                                                         \
        const int _k0 = (KT) * 16;                                               \
        _Pragma("unroll")                                                        \
        for (int _i = 0; _i < 2; _i++) {                                         \
            const int _row = lr + _i * 64;                                       \
            const float* _gx = X + (size_t)(m0 + _row) * D_ + _k0 + sg;          \
            uint32_t _sa = (uint32_t)__cvta_generic_to_shared(&As[BUF][_row][sg]);\
            asm volatile("cp.async.cg.shared.global [%0], [%1], 16;"             \
                         :: "r"(_sa), "l"(_gx));                                 \
            const float* _gw = W + (size_t)(n0 + _row) * D_ + _k0 + sg;          \
            uint32_t _sb = (uint32_t)__cvta_generic_to_shared(&Bs[BUF][_row][sg]);\
            asm volatile("cp.async.cg.shared.global [%0], [%1], 16;"             \
                         :: "r"(_sb), "l"(_gw));                                 \
        }                                                                        \
        asm volatile("cp.async.commit_group;");                                  \
    } while (0)

    ISSUE_STAGE(0, 0);

    const int NKT = D_ / 16;   // 64
    for (int kt = 0; kt < NKT; kt++) {
        asm volatile("cp.async.wait_group 0;");
        __syncthreads();
        if (kt + 1 < NKT) ISSUE_STAGE(kt + 1, (kt + 1) & 1);

        const int buf = kt & 1;
#pragma unroll
        for (int s = 0; s < 2; s++) {
            const int kk = s * 8;
            uint32_t a[4][4], b[4][2];
#pragma unroll
            for (int mt = 0; mt < 4; mt++) {
                const int row = wm * 64 + mt * 16 + g;
                a[mt][0] = f2tf32(As[buf][row    ][kk + tg    ]);
                a[mt][1] = f2tf32(As[buf][row + 8][kk + tg    ]);
                a[mt][2] = f2tf32(As[buf][row    ][kk + tg + 4]);
                a[mt][3] = f2tf32(As[buf][row + 8][kk + tg + 4]);
            }
#pragma unroll
            for (int nt = 0; nt < 4; nt++) {
                const int col = wn * 32 + nt * 8 + g;
                b[nt][0] = f2tf32(Bs[buf][col][kk + tg    ]);
                b[nt][1] = f2tf32(Bs[buf][col][kk + tg + 4]);
            }
#pragma unroll
            for (int mt = 0; mt < 4; mt++)
#pragma unroll
                for (int nt = 0; nt < 4; nt++) {
                    asm volatile(
                        "mma.sync.aligned.m16n8k8.row.col.f32.tf32.tf32.f32 "
                        "{%0,%1,%2,%3}, {%4,%5,%6,%7}, {%8,%9}, {%0,%1,%2,%3};"
                        : "+f"(c[mt][nt][0]), "+f"(c[mt][nt][1]),
                          "+f"(c[mt][nt][2]), "+f"(c[mt][nt][3])
                        : "r"(a[mt][0]), "r"(a[mt][1]), "r"(a[mt][2]), "r"(a[mt][3]),
                          "r"(b[nt][0]), "r"(b[nt][1]));
                }
        }
        __syncthreads();
    }
#undef ISSUE_STAGE

    // Epilogue: c0,c1 -> (row, col..col+1), c2,c3 -> (row+8, col..col+1)
#pragma unroll
    for (int nt = 0; nt < 4; nt++) {
        const int col = n0 + wn * 32 + nt * 8 + tg * 2;
        const float2 bv = *(const float2*)&bias[col];
#pragma unroll
        for (int mt = 0; mt < 4; mt++) {
            const int row = m0 + wm * 64 + mt * 16 + g;
            float2 o0, o1;
            o0.x = c[mt][nt][0] + bv.x; o0.y = c[mt][nt][1] + bv.y;
            o1.x = c[mt][nt][2] + bv.x; o1.y = c[mt][nt][3] + bv.y;
            *(float2*)(Y + (size_t)row * D_ + col)       = o0;
            *(float2*)(Y + (size_t)(row + 8) * D_ + col) = o1;
        }
    }
}

// ---------------------------------------------------------------------------
// Flash attention, causal, fp32 (unchanged from round 4 — passes at 1.2e-6).
// ---------------------------------------------------------------------------
#define FLASH_SMEM_FLOATS (128*65 + 64*65 + 64*65 + 128*65)
#define FLASH_SMEM_BYTES  (FLASH_SMEM_FLOATS * 4)

__device__ __forceinline__ float redmax16(float v) {
#pragma unroll
    for (int o = 8; o >= 1; o >>= 1)
        v = fmaxf(v, __shfl_xor_sync(0xffffffffu, v, o));
    return v;
}
__device__ __forceinline__ float redsum16(float v) {
#pragma unroll
    for (int o = 8; o >= 1; o >>= 1)
        v += __shfl_xor_sync(0xffffffffu, v, o);
    return v;
}

__global__ __launch_bounds__(256)
void flash_attn_causal(const float* __restrict__ Qp, const float* __restrict__ Kp,
                       const float* __restrict__ Vp, float* __restrict__ Ao) {
    extern __shared__ float sm[];
    float* Qs = sm;                 // [128][65]
    float* Ks = Qs + 128*65;        // [64][65]  transposed: Ks[d*65 + c]
    float* Vs = Ks + 64*65;         // [64][65]  Vs[c*65 + d]
    float* Ps = Vs + 64*65;         // [128][65]

    const int tid = threadIdx.x;
    const int tx  = tid & 15;
    const int ty  = tid >> 4;
    const int qb  = blockIdx.x;
    const int h   = blockIdx.y;
    const int b   = blockIdx.z;

    const int rowbase = b * L_ + qb * 128;
    const int colbase = h * DK_;

    {
        const int r     = tid >> 1;
        const int dbase = (tid & 1) * 32;
        const float* src = Qp + (size_t)(rowbase + r) * D_ + colbase + dbase;
        float* dst = Qs + r * 65 + dbase;
#pragma unroll
        for (int i = 0; i < 8; i++) {
            float4 vq = *(const float4*)(src + i * 4);
            dst[i*4+0] = vq.x * 0.125f; dst[i*4+1] = vq.y * 0.125f;
            dst[i*4+2] = vq.z * 0.125f; dst[i*4+3] = vq.w * 0.125f;
        }
    }

    float m[8], l[8], O[8][4];
#pragma unroll
    for (int i = 0; i < 8; i++) {
        m[i] = -1e30f; l[i] = 0.f;
        O[i][0] = O[i][1] = O[i][2] = O[i][3] = 0.f;
    }

    const int nkb = 2 * qb + 2;
    const int kvc = tid >> 2;
    const int kvd = (tid & 3) * 16;

    for (int kb = 0; kb < nkb; kb++) {
        {
            const size_t grow = (size_t)(b * L_ + kb * 64 + kvc) * D_ + colbase + kvd;
            const float* ksrc = Kp + grow;
            const float* vsrc = Vp + grow;
#pragma unroll
            for (int i = 0; i < 4; i++) {
                float4 kv = *(const float4*)(ksrc + i * 4);
                const int d0 = kvd + i * 4;
                Ks[(d0+0)*65 + kvc] = kv.x;
                Ks[(d0+1)*65 + kvc] = kv.y;
                Ks[(d0+2)*65 + kvc] = kv.z;
                Ks[(d0+3)*65 + kvc] = kv.w;
                float4 vv = *(const float4*)(vsrc + i * 4);
                float* vd = Vs + kvc * 65 + d0;
                vd[0] = vv.x; vd[1] = vv.y; vd[2] = vv.z; vd[3] = vv.w;
            }
        }
        __syncthreads();

        float S[8][4];
#pragma unroll
        for (int i = 0; i < 8; i++)
            S[i][0] = S[i][1] = S[i][2] = S[i][3] = 0.f;

        const float* qptr = Qs + ty * 8 * 65;
        const float* kptr = Ks + tx * 4;
#pragma unroll 8
        for (int d = 0; d < 64; d++) {
            const float rk0 = kptr[d*65 + 0];
            const float rk1 = kptr[d*65 + 1];
            const float rk2 = kptr[d*65 + 2];
            const float rk3 = kptr[d*65 + 3];
#pragma unroll
            for (int i = 0; i < 8; i++) {
                const float rq = qptr[i*65 + d];
                S[i][0] += rq * rk0; S[i][1] += rq * rk1;
                S[i][2] += rq * rk2; S[i][3] += rq * rk3;
            }
        }

        if (kb >= 2 * qb) {
#pragma unroll
            for (int i = 0; i < 8; i++) {
                const int qg = qb * 128 + ty * 8 + i;
#pragma unroll
                for (int j = 0; j < 4; j++) {
                    const int kg = kb * 64 + tx * 4 + j;
                    if (kg > qg) S[i][j] = -1e30f;
                }
            }
        }

        float* pptr = Ps + ty * 8 * 65 + tx * 4;
#pragma unroll
        for (int i = 0; i < 8; i++) {
            float mx = fmaxf(fmaxf(S[i][0], S[i][1]), fmaxf(S[i][2], S[i][3]));
            mx = redmax16(mx);
            const float mn = fmaxf(m[i], mx);
            const float alpha = __expf(m[i] - mn);
            const float p0 = __expf(S[i][0] - mn);
            const float p1 = __expf(S[i][1] - mn);
            const float p2 = __expf(S[i][2] - mn);
            const float p3 = __expf(S[i][3] - mn);
            float rs = p0 + p1 + p2 + p3;
            rs = redsum16(rs);
            l[i] = l[i] * alpha + rs;
            m[i] = mn;
            O[i][0] *= alpha; O[i][1] *= alpha;
            O[i][2] *= alpha; O[i][3] *= alpha;
            pptr[i*65 + 0] = p0; pptr[i*65 + 1] = p1;
            pptr[i*65 + 2] = p2; pptr[i*65 + 3] = p3;
        }
        __syncthreads();

        const float* ppr = Ps + ty * 8 * 65;
        const float* vpr = Vs + tx * 4;
#pragma unroll 8
        for (int ccol = 0; ccol < 64; ccol++) {
            const float rv0 = vpr[ccol*65 + 0];
            const float rv1 = vpr[ccol*65 + 1];
            const float rv2 = vpr[ccol*65 + 2];
            const float rv3 = vpr[ccol*65 + 3];
#pragma unroll
            for (int i = 0; i < 8; i++) {
                const float rp = ppr[i*65 + ccol];
                O[i][0] += rp * rv0; O[i][1] += rp * rv1;
                O[i][2] += rp * rv2; O[i][3] += rp * rv3;
            }
        }
        __syncthreads();
    }

#pragma unroll
    for (int i = 0; i < 8; i++) {
        const float inv = 1.0f / l[i];
        float* dst = Ao + (size_t)(rowbase + ty * 8 + i) * D_ + colbase + tx * 4;
        dst[0] = O[i][0] * inv; dst[1] = O[i][1] * inv;
        dst[2] = O[i][2] * inv; dst[3] = O[i][3] * inv;
    }
}

// ---------------------------------------------------------------------------
extern "C" void kernel_launch(void* const* d_in, const int* in_sizes, int n_in,
                              void* d_out, int out_size) {
    (void)in_sizes; (void)n_in; (void)out_size;
    const float* q    = (const float*)d_in[0];
    const float* k    = (const float*)d_in[1];
    const float* v    = (const float*)d_in[2];
    const float* wq_w = (const float*)d_in[3];
    const float* wq_b = (const float*)d_in[4];
    const float* wk_w = (const float*)d_in[5];
    const float* wk_b = (const float*)d_in[6];
    const float* wv_w = (const float*)d_in[7];
    const float* wv_b = (const float*)d_in[8];
    const float* wo_w = (const float*)d_in[9];
    const float* wo_b = (const float*)d_in[10];

    float *Qp, *Kp, *Vp, *Ao;
    cudaGetSymbolAddress((void**)&Qp, g_Qp);
    cudaGetSymbolAddress((void**)&Kp, g_Kp);
    cudaGetSymbolAddress((void**)&Vp, g_Vp);
    cudaGetSymbolAddress((void**)&Ao, g_Ao);

    dim3 gg(D_/128, M_/128);   // (8, 64)
    gemm_tf32_nt_bias<<<gg, 256>>>(q, wq_w, wq_b, Qp);
    gemm_tf32_nt_bias<<<gg, 256>>>(k, wk_w, wk_b, Kp);
    gemm_tf32_nt_bias<<<gg, 256>>>(v, wv_w, wv_b, Vp);

    cudaFuncSetAttribute(flash_attn_causal,
                         cudaFuncAttributeMaxDynamicSharedMemorySize,
                         FLASH_SMEM_BYTES);
    flash_attn_causal<<<dim3(L_/128, H_, B_), 256, FLASH_SMEM_BYTES>>>(Qp, Kp, Vp, Ao);

    gemm_tf32_nt_bias<<<gg, 256>>>(Ao, wo_w, wo_b, (float*)d_out);
}

// round 8
// speedup vs baseline: 2.8351x; 1.6846x over previous
#include <cuda_runtime.h>
#include <cstdint>

#define B_  4
#define L_  2048
#define D_  1024
#define H_  16
#define DK_ 64
#define M_  (B_*L_)   // 8192

// Scratch (device globals — no allocation allowed)
__device__ float g_Qp[M_*D_];
__device__ float g_Kp[M_*D_];
__device__ float g_Vp[M_*D_];
__device__ float g_Ao[M_*D_];

__device__ __forceinline__ uint32_t f2tf32(float f) {
    uint32_t r;
    asm("cvt.rna.tf32.f32 %0, %1;" : "=r"(r) : "f"(f));
    return r;
}
__device__ __forceinline__ float tf32r(float f) {   // tf32-rounded value as float
    return __uint_as_float(f2tf32(f));
}

// ---------------------------------------------------------------------------
// TF32 tensor-core GEMM: Y[M,N] = X[M,K] * W[N,K]^T + bias[N]  (unchanged)
// ---------------------------------------------------------------------------
__global__ __launch_bounds__(256)
void gemm_tf32_nt_bias(const float* __restrict__ X, const float* __restrict__ W,
                       const float* __restrict__ bias, float* __restrict__ Y) {
    __shared__ float As[2][128][20];
    __shared__ float Bs[2][128][20];

    const int tid  = threadIdx.x;
    const int m0   = blockIdx.y * 128;
    const int n0   = blockIdx.x * 128;
    const int warp = tid >> 5;
    const int lane = tid & 31;
    const int wm   = warp >> 2;
    const int wn   = warp & 3;
    const int g    = lane >> 2;
    const int tg   = lane & 3;

    const int lr = tid >> 2;
    const int sg = (tid & 3) * 4;

    float c[4][4][4];
#pragma unroll
    for (int mt = 0; mt < 4; mt++)
#pragma unroll
        for (int nt = 0; nt < 4; nt++)
#pragma unroll
            for (int e = 0; e < 4; e++) c[mt][nt][e] = 0.f;

#define ISSUE_STAGE(KT, BUF)                                                     \
    do {                                                                         \
        const int _k0 = (KT) * 16;                                               \
        _Pragma("unroll")                                                        \
        for (int _i = 0; _i < 2; _i++) {                                         \
            const int _row = lr + _i * 64;                                       \
            const float* _gx = X + (size_t)(m0 + _row) * D_ + _k0 + sg;          \
            uint32_t _sa = (uint32_t)__cvta_generic_to_shared(&As[BUF][_row][sg]);\
            asm volatile("cp.async.cg.shared.global [%0], [%1], 16;"             \
                         :: "r"(_sa), "l"(_gx));                                 \
            const float* _gw = W + (size_t)(n0 + _row) * D_ + _k0 + sg;          \
            uint32_t _sb = (uint32_t)__cvta_generic_to_shared(&Bs[BUF][_row][sg]);\
            asm volatile("cp.async.cg.shared.global [%0], [%1], 16;"             \
                         :: "r"(_sb), "l"(_gw));                                 \
        }                                                                        \
        asm volatile("cp.async.commit_group;");                                  \
    } while (0)

    ISSUE_STAGE(0, 0);

    const int NKT = D_ / 16;
    for (int kt = 0; kt < NKT; kt++) {
        asm volatile("cp.async.wait_group 0;");
        __syncthreads();
        if (kt + 1 < NKT) ISSUE_STAGE(kt + 1, (kt + 1) & 1);

        const int buf = kt & 1;
#pragma unroll
        for (int s = 0; s < 2; s++) {
            const int kk = s * 8;
            uint32_t a[4][4], b[4][2];
#pragma unroll
            for (int mt = 0; mt < 4; mt++) {
                const int row = wm * 64 + mt * 16 + g;
                a[mt][0] = f2tf32(As[buf][row    ][kk + tg    ]);
                a[mt][1] = f2tf32(As[buf][row + 8][kk + tg    ]);
                a[mt][2] = f2tf32(As[buf][row    ][kk + tg + 4]);
                a[mt][3] = f2tf32(As[buf][row + 8][kk + tg + 4]);
            }
#pragma unroll
            for (int nt = 0; nt < 4; nt++) {
                const int col = wn * 32 + nt * 8 + g;
                b[nt][0] = f2tf32(Bs[buf][col][kk + tg    ]);
                b[nt][1] = f2tf32(Bs[buf][col][kk + tg + 4]);
            }
#pragma unroll
            for (int mt = 0; mt < 4; mt++)
#pragma unroll
                for (int nt = 0; nt < 4; nt++) {
                    asm volatile(
                        "mma.sync.aligned.m16n8k8.row.col.f32.tf32.tf32.f32 "
                        "{%0,%1,%2,%3}, {%4,%5,%6,%7}, {%8,%9}, {%0,%1,%2,%3};"
                        : "+f"(c[mt][nt][0]), "+f"(c[mt][nt][1]),
                          "+f"(c[mt][nt][2]), "+f"(c[mt][nt][3])
                        : "r"(a[mt][0]), "r"(a[mt][1]), "r"(a[mt][2]), "r"(a[mt][3]),
                          "r"(b[nt][0]), "r"(b[nt][1]));
                }
        }
        __syncthreads();
    }
#undef ISSUE_STAGE

#pragma unroll
    for (int nt = 0; nt < 4; nt++) {
        const int col = n0 + wn * 32 + nt * 8 + tg * 2;
        const float2 bv = *(const float2*)&bias[col];
#pragma unroll
        for (int mt = 0; mt < 4; mt++) {
            const int row = m0 + wm * 64 + mt * 16 + g;
            float2 o0, o1;
            o0.x = c[mt][nt][0] + bv.x; o0.y = c[mt][nt][1] + bv.y;
            o1.x = c[mt][nt][2] + bv.x; o1.y = c[mt][nt][3] + bv.y;
            *(float2*)(Y + (size_t)row * D_ + col)       = o0;
            *(float2*)(Y + (size_t)(row + 8) * D_ + col) = o1;
        }
    }
}

// ---------------------------------------------------------------------------
// Flash attention, causal, TF32 tensor cores.
// Grid: (L/128, H, B), 256 threads = 8 warps; warp w owns q-rows [w*16, w*16+16).
// Smem (pitch 68 floats -> scalar fragment loads hit bank = 4g+tg, conflict-free):
//   Qs[128][68]  (Q * 0.125, tf32-rounded)    -- A operand of S = Q K^T
//   Ks[ 64][68]  K natural [c][d], tf32       -- B operand of S (n=c, k=d)
//   Vt[ 64][68]  V transposed [d][c], tf32    -- B operand of O += P V (n=d, k=c)
//   Ps[128][68]  P tf32                       -- A operand of P V
// ---------------------------------------------------------------------------
#define PITCH 68
#define FLASH_SMEM_FLOATS ((128 + 64 + 64 + 128) * PITCH)
#define FLASH_SMEM_BYTES  (FLASH_SMEM_FLOATS * 4)

__device__ __forceinline__ float redmax4(float v) {
    v = fmaxf(v, __shfl_xor_sync(0xffffffffu, v, 1));
    v = fmaxf(v, __shfl_xor_sync(0xffffffffu, v, 2));
    return v;
}
__device__ __forceinline__ float redsum4(float v) {
    v += __shfl_xor_sync(0xffffffffu, v, 1);
    v += __shfl_xor_sync(0xffffffffu, v, 2);
    return v;
}

__global__ __launch_bounds__(256)
void flash_attn_tc(const float* __restrict__ Qp, const float* __restrict__ Kp,
                   const float* __restrict__ Vp, float* __restrict__ Ao) {
    extern __shared__ float sm[];
    float* Qs = sm;                  // [128][PITCH]
    float* Ks = Qs + 128 * PITCH;    // [64][PITCH]
    float* Vt = Ks + 64 * PITCH;     // [64][PITCH]
    float* Ps = Vt + 64 * PITCH;     // [128][PITCH]

    const int tid  = threadIdx.x;
    const int warp = tid >> 5;
    const int lane = tid & 31;
    const int g    = lane >> 2;      // 0..7
    const int tg   = lane & 3;       // 0..3
    const int qb   = blockIdx.x;
    const int h    = blockIdx.y;
    const int b    = blockIdx.z;

    const int rowbase = b * L_ + qb * 128;
    const int colbase = h * DK_;
    const int wr0     = warp * 16;          // this warp's q-row base (local)

    // ---- load Q (scaled, tf32-rounded) ----
    {
        const int r     = tid >> 1;
        const int dbase = (tid & 1) * 32;
        const float* src = Qp + (size_t)(rowbase + r) * D_ + colbase + dbase;
        float* dst = Qs + r * PITCH + dbase;
#pragma unroll
        for (int i = 0; i < 8; i++) {
            float4 vq = *(const float4*)(src + i * 4);
            dst[i*4+0] = tf32r(vq.x * 0.125f); dst[i*4+1] = tf32r(vq.y * 0.125f);
            dst[i*4+2] = tf32r(vq.z * 0.125f); dst[i*4+3] = tf32r(vq.w * 0.125f);
        }
    }

    float m0 = -1e30f, m1 = -1e30f, l0 = 0.f, l1 = 0.f;
    float O[8][4];
#pragma unroll
    for (int dt = 0; dt < 8; dt++)
#pragma unroll
        for (int e = 0; e < 4; e++) O[dt][e] = 0.f;

    const int nkb = 2 * qb + 2;
    const int kvc = tid >> 2;                // 0..63: key row this thread loads

    for (int kb = 0; kb < nkb; kb++) {
        // ---- load K [c][d] and V transposed [d][c], both tf32-rounded ----
        {
            const size_t grow = (size_t)(b * L_ + kb * 64 + kvc) * D_ + colbase;
            const float* ksrc = Kp + grow;
            const float* vsrc = Vp + grow;
            float* krow = Ks + kvc * PITCH;
#pragma unroll
            for (int i = 0; i < 4; i++) {
                const int d0 = (tid & 3) * 4 + i * 16;
                float4 kv = *(const float4*)(ksrc + d0);
                krow[d0+0] = tf32r(kv.x); krow[d0+1] = tf32r(kv.y);
                krow[d0+2] = tf32r(kv.z); krow[d0+3] = tf32r(kv.w);
                float4 vv = *(const float4*)(vsrc + d0);
                Vt[(d0+0)*PITCH + kvc] = tf32r(vv.x);
                Vt[(d0+1)*PITCH + kvc] = tf32r(vv.y);
                Vt[(d0+2)*PITCH + kvc] = tf32r(vv.z);
                Vt[(d0+3)*PITCH + kvc] = tf32r(vv.w);
            }
        }
        __syncthreads();

        // ---- S = Q K^T : 8 n-tiles x 8 k-steps of m16n8k8 ----
        float s[8][4];
#pragma unroll
        for (int nt = 0; nt < 8; nt++)
#pragma unroll
            for (int e = 0; e < 4; e++) s[nt][e] = 0.f;

#pragma unroll
        for (int ks = 0; ks < 8; ks++) {
            const int kk = ks * 8;
            uint32_t a0 = __float_as_uint(Qs[(wr0 + g    ) * PITCH + kk + tg    ]);
            uint32_t a1 = __float_as_uint(Qs[(wr0 + g + 8) * PITCH + kk + tg    ]);
            uint32_t a2 = __float_as_uint(Qs[(wr0 + g    ) * PITCH + kk + tg + 4]);
            uint32_t a3 = __float_as_uint(Qs[(wr0 + g + 8) * PITCH + kk + tg + 4]);
#pragma unroll
            for (int nt = 0; nt < 8; nt++) {
                uint32_t b0 = __float_as_uint(Ks[(nt*8 + g) * PITCH + kk + tg    ]);
                uint32_t b1 = __float_as_uint(Ks[(nt*8 + g) * PITCH + kk + tg + 4]);
                asm volatile(
                    "mma.sync.aligned.m16n8k8.row.col.f32.tf32.tf32.f32 "
                    "{%0,%1,%2,%3}, {%4,%5,%6,%7}, {%8,%9}, {%0,%1,%2,%3};"
                    : "+f"(s[nt][0]), "+f"(s[nt][1]), "+f"(s[nt][2]), "+f"(s[nt][3])
                    : "r"(a0), "r"(a1), "r"(a2), "r"(a3), "r"(b0), "r"(b1));
            }
        }

        // ---- causal mask (only the two diagonal-touching blocks) ----
        if (kb >= 2 * qb) {
            const int qg0 = qb * 128 + wr0 + g;
            const int qg1 = qg0 + 8;
#pragma unroll
            for (int nt = 0; nt < 8; nt++) {
                const int kg = kb * 64 + nt * 8 + 2 * tg;
                if (kg     > qg0) s[nt][0] = -1e30f;
                if (kg + 1 > qg0) s[nt][1] = -1e30f;
                if (kg     > qg1) s[nt][2] = -1e30f;
                if (kg + 1 > qg1) s[nt][3] = -1e30f;
            }
        }

        // ---- online softmax (rows g and g+8; reduce over 4-lane group) ----
        {
            float mx0 = -1e30f, mx1 = -1e30f;
#pragma unroll
            for (int nt = 0; nt < 8; nt++) {
                mx0 = fmaxf(mx0, fmaxf(s[nt][0], s[nt][1]));
                mx1 = fmaxf(mx1, fmaxf(s[nt][2], s[nt][3]));
            }
            mx0 = redmax4(mx0); mx1 = redmax4(mx1);
            const float mn0 = fmaxf(m0, mx0), mn1 = fmaxf(m1, mx1);
            const float al0 = __expf(m0 - mn0), al1 = __expf(m1 - mn1);

            float* p0 = Ps + (wr0 + g    ) * PITCH + 2 * tg;
            float* p1 = Ps + (wr0 + g + 8) * PITCH + 2 * tg;
            float sum0 = 0.f, sum1 = 0.f;
#pragma unroll
            for (int nt = 0; nt < 8; nt++) {
                const float e0 = __expf(s[nt][0] - mn0);
                const float e1 = __expf(s[nt][1] - mn0);
                const float e2 = __expf(s[nt][2] - mn1);
                const float e3 = __expf(s[nt][3] - mn1);
                sum0 += e0 + e1; sum1 += e2 + e3;
                p0[nt*8 + 0] = tf32r(e0); p0[nt*8 + 1] = tf32r(e1);
                p1[nt*8 + 0] = tf32r(e2); p1[nt*8 + 1] = tf32r(e3);
            }
            sum0 = redsum4(sum0); sum1 = redsum4(sum1);
            l0 = l0 * al0 + sum0; l1 = l1 * al1 + sum1;
            m0 = mn0; m1 = mn1;
#pragma unroll
            for (int dt = 0; dt < 8; dt++) {
                O[dt][0] *= al0; O[dt][1] *= al0;
                O[dt][2] *= al1; O[dt][3] *= al1;
            }
        }
        __syncwarp();   // P rows are produced & consumed within this warp only

        // ---- O += P V : 8 d-tiles x 8 k-steps ----
#pragma unroll
        for (int ks = 0; ks < 8; ks++) {
            const int kk = ks * 8;
            uint32_t a0 = __float_as_uint(Ps[(wr0 + g    ) * PITCH + kk + tg    ]);
            uint32_t a1 = __float_as_uint(Ps[(wr0 + g + 8) * PITCH + kk + tg    ]);
            uint32_t a2 = __float_as_uint(Ps[(wr0 + g    ) * PITCH + kk + tg + 4]);
            uint32_t a3 = __float_as_uint(Ps[(wr0 + g + 8) * PITCH + kk + tg + 4]);
#pragma unroll
            for (int dt = 0; dt < 8; dt++) {
                uint32_t b0 = __float_as_uint(Vt[(dt*8 + g) * PITCH + kk + tg    ]);
                uint32_t b1 = __float_as_uint(Vt[(dt*8 + g) * PITCH + kk + tg + 4]);
                asm volatile(
                    "mma.sync.aligned.m16n8k8.row.col.f32.tf32.tf32.f32 "
                    "{%0,%1,%2,%3}, {%4,%5,%6,%7}, {%8,%9}, {%0,%1,%2,%3};"
                    : "+f"(O[dt][0]), "+f"(O[dt][1]), "+f"(O[dt][2]), "+f"(O[dt][3])
                    : "r"(a0), "r"(a1), "r"(a2), "r"(a3), "r"(b0), "r"(b1));
            }
        }
        __syncthreads();   // before next iteration overwrites Ks/Vt
    }

    // ---- normalize and write out ----
    {
        const float inv0 = 1.0f / l0;
        const float inv1 = 1.0f / l1;
        float* d0 = Ao + (size_t)(rowbase + wr0 + g    ) * D_ + colbase + 2 * tg;
        float* d1 = Ao + (size_t)(rowbase + wr0 + g + 8) * D_ + colbase + 2 * tg;
#pragma unroll
        for (int dt = 0; dt < 8; dt++) {
            float2 o0, o1;
            o0.x = O[dt][0] * inv0; o0.y = O[dt][1] * inv0;
            o1.x = O[dt][2] * inv1; o1.y = O[dt][3] * inv1;
            *(float2*)(d0 + dt * 8) = o0;
            *(float2*)(d1 + dt * 8) = o1;
        }
    }
}

// ---------------------------------------------------------------------------
extern "C" void kernel_launch(void* const* d_in, const int* in_sizes, int n_in,
                              void* d_out, int out_size) {
    (void)in_sizes; (void)n_in; (void)out_size;
    const float* q    = (const float*)d_in[0];
    const float* k    = (const float*)d_in[1];
    const float* v    = (const float*)d_in[2];
    const float* wq_w = (const float*)d_in[3];
    const float* wq_b = (const float*)d_in[4];
    const float* wk_w = (const float*)d_in[5];
    const float* wk_b = (const float*)d_in[6];
    const float* wv_w = (const float*)d_in[7];
    const float* wv_b = (const float*)d_in[8];
    const float* wo_w = (const float*)d_in[9];
    const float* wo_b = (const float*)d_in[10];

    float *Qp, *Kp, *Vp, *Ao;
    cudaGetSymbolAddress((void**)&Qp, g_Qp);
    cudaGetSymbolAddress((void**)&Kp, g_Kp);
    cudaGetSymbolAddress((void**)&Vp, g_Vp);
    cudaGetSymbolAddress((void**)&Ao, g_Ao);

    dim3 gg(D_/128, M_/128);   // (8, 64)
    gemm_tf32_nt_bias<<<gg, 256>>>(q, wq_w, wq_b, Qp);
    gemm_tf32_nt_bias<<<gg, 256>>>(k, wk_w, wk_b, Kp);
    gemm_tf32_nt_bias<<<gg, 256>>>(v, wv_w, wv_b, Vp);

    cudaFuncSetAttribute(flash_attn_tc,
                         cudaFuncAttributeMaxDynamicSharedMemorySize,
                         FLASH_SMEM_BYTES);
    flash_attn_tc<<<dim3(L_/128, H_, B_), 256, FLASH_SMEM_BYTES>>>(Qp, Kp, Vp, Ao);

    gemm_tf32_nt_bias<<<gg, 256>>>(Ao, wo_w, wo_b, (float*)d_out);
}